// round 15
// baseline (speedup 1.0000x reference)
#include <cuda_runtime.h>
#include <cuda_bf16.h>
#include <cuda_fp16.h>
#include <cstdint>

#define NN 100000
#define EE 1000000
#define DD 64

// ---------------- device scratch ----------------
__device__ int      g_deg[NN];
__device__ int      g_cursor[NN];
__device__ int      g_rowptr[NN + 1];
__device__ int      g_bsum[128];
__device__ int      g_csrc[EE];
__device__ float    g_invdeg[NN];
__device__ __half   g_p[NN * DD];      // fp16 lin_l partials, ping
__device__ __half   g_p2[NN * DD];     // fp16 lin_l partials, pong
__device__ float    g_tmp[NN * DD];
// W' fragment-major fp16: per layer 64 frag-groups x 32 lanes of uint2
__device__ uint2    g_Wf[3 * 2048];

__device__ __forceinline__ unsigned pack_h2(float a, float b) {
    __half2 t = __floats2half2_rn(a, b);
    return *(unsigned*)&t;
}
__device__ __forceinline__ float4 h4_to_f4(uint2 v) {
    float2 a = __half22float2(*(__half2*)&v.x);
    float2 b = __half22float2(*(__half2*)&v.y);
    return make_float4(a.x, a.y, b.x, b.y);
}

// ---------------- CSR construction ----------------
__global__ void k_count(const int* __restrict__ dst, int e) {
    int i = blockIdx.x * blockDim.x + threadIdx.x;
    if (i < e) atomicAdd(&g_deg[__ldg(dst + i)], 1);
}

__global__ void k_scanA(int n) {
    __shared__ int wsum[32];
    int t = threadIdx.x;
    int i = blockIdx.x * 1024 + t;
    int v = (i < n) ? g_deg[i] : 0;
    int lane = t & 31, w = t >> 5;
    int s = v;
    #pragma unroll
    for (int off = 1; off < 32; off <<= 1) {
        int u = __shfl_up_sync(0xffffffffu, s, off);
        if (lane >= off) s += u;
    }
    if (lane == 31) wsum[w] = s;
    __syncthreads();
    if (w == 0) {
        int ws = wsum[lane];
        #pragma unroll
        for (int off = 1; off < 32; off <<= 1) {
            int u = __shfl_up_sync(0xffffffffu, ws, off);
            if (lane >= off) ws += u;
        }
        wsum[lane] = ws;
    }
    __syncthreads();
    int base = (w > 0) ? wsum[w - 1] : 0;
    int incl = base + s;
    if (i < n) g_rowptr[i] = incl - v;          // exclusive
    if (t == 1023) g_bsum[blockIdx.x] = incl;
}

__global__ void k_scanB(int nb) {
    __shared__ int wsum[4];
    int t = threadIdx.x;                        // 128 threads
    int lane = t & 31, w = t >> 5;
    int v = (t < nb) ? g_bsum[t] : 0;
    int s = v;
    #pragma unroll
    for (int off = 1; off < 32; off <<= 1) {
        int u = __shfl_up_sync(0xffffffffu, s, off);
        if (lane >= off) s += u;
    }
    if (lane == 31) wsum[w] = s;
    __syncthreads();
    int base = 0;
    for (int q = 0; q < w; q++) base += wsum[q];
    if (t < nb) g_bsum[t] = base + s - v;       // exclusive
}

__global__ void k_scanC(int n, int e) {
    int i = blockIdx.x * blockDim.x + threadIdx.x;
    if (i < n) {
        g_rowptr[i] += g_bsum[i >> 10];
        g_invdeg[i] = 1.0f / fmaxf((float)g_deg[i], 1.0f);
    }
    if (i == 0) g_rowptr[n] = e;
}

__global__ void k_fill(const int* __restrict__ src, const int* __restrict__ dst, int e) {
    int i = blockIdx.x * blockDim.x + threadIdx.x;
    if (i < e) {
        int d = __ldg(dst + i);
        int pos = g_rowptr[d] + atomicAdd(&g_cursor[d], 1);
        g_csrc[pos] = __ldg(src + i);
    }
}

// ---------------- W' precompute into fragment-major fp16 layout ----------------
__global__ void k_prepW(const float* __restrict__ Wr, const float* __restrict__ Wl) {
    int idx = blockIdx.x * blockDim.x + threadIdx.x;
    if (idx >= 3 * 2048) return;
    int l = idx / 2048;
    int rem = idx - l * 2048;
    int fg = rem >> 5;
    int lane = rem & 31;
    int cg = fg >> 5;
    int nt = (fg >> 2) & 7;
    int ks = fg & 3;
    int c = cg * 64 + nt * 8 + (lane >> 2);
    int q = lane & 3;
    int k0 = 16 * ks + 2 * q;
    int k1 = k0 + 8;
    const float* Wsrc = (c < 64) ? (Wr + l * 4096 + c * 64) : (Wl + l * 4096 + (c - 64) * 64);
    uint2 v;
    v.x = pack_h2(__ldg(Wsrc + k0), __ldg(Wsrc + k0 + 1));
    v.y = pack_h2(__ldg(Wsrc + k1), __ldg(Wsrc + k1 + 1));
    g_Wf[idx] = v;
}

__device__ __forceinline__ void mma_f16(float* c, unsigned a0, unsigned a1, unsigned a2,
                                        unsigned a3, unsigned b0, unsigned b1) {
    asm volatile(
        "mma.sync.aligned.m16n8k16.row.col.f32.f16.f16.f32 "
        "{%0,%1,%2,%3}, {%4,%5,%6,%7}, {%8,%9}, {%0,%1,%2,%3};"
        : "+f"(c[0]), "+f"(c[1]), "+f"(c[2]), "+f"(c[3])
        : "r"(a0), "r"(a1), "r"(a2), "r"(a3), "r"(b0), "r"(b1));
}

// ---------------- layer-0 GEMM (R12 config): tmp = x@Wr^T + bl ; p = x@Wl^T ----------------
#define EPS 68

__global__ void __launch_bounds__(256, 3) k_mma(const float* __restrict__ A,
                                                const uint2* __restrict__ Wf,
                                                const float* __restrict__ bl,
                                                float* __restrict__ tmp, __half* __restrict__ p, int n) {
    __shared__ float buf[64 * EPS];
    int tid = threadIdx.x;
    int i0 = blockIdx.x * 64;

    int w = tid >> 5, lane = tid & 31;
    int wr = (w >> 1) * 16;
    int cg = w & 1;
    int g = lane >> 2, q = lane & 3;

    int r0 = i0 + wr + g, r1 = r0 + 8;
    bool v0 = r0 < n, v1 = r1 < n;
    const float* A0 = A + (size_t)r0 * 64;
    const float* A1 = A + (size_t)r1 * 64;

    float acc[8][4];
    #pragma unroll
    for (int nt = 0; nt < 8; nt++)
        #pragma unroll
        for (int z = 0; z < 4; z++) acc[nt][z] = 0.f;

    const uint2* Wbase = Wf + cg * 1024 + lane;

    #pragma unroll
    for (int ks = 0; ks < 4; ks++) {
        int k0 = ks * 16 + 2 * q;
        float2 z = make_float2(0.f, 0.f);
        float2 x00 = v0 ? __ldg((const float2*)(A0 + k0))     : z;
        float2 x10 = v1 ? __ldg((const float2*)(A1 + k0))     : z;
        float2 x01 = v0 ? __ldg((const float2*)(A0 + k0 + 8)) : z;
        float2 x11 = v1 ? __ldg((const float2*)(A1 + k0 + 8)) : z;

        unsigned ah0 = pack_h2(x00.x, x00.y);
        unsigned ah1 = pack_h2(x10.x, x10.y);
        unsigned ah2 = pack_h2(x01.x, x01.y);
        unsigned ah3 = pack_h2(x11.x, x11.y);
        float2 f0 = __half22float2(*(__half2*)&ah0);
        float2 f1 = __half22float2(*(__half2*)&ah1);
        float2 f2 = __half22float2(*(__half2*)&ah2);
        float2 f3 = __half22float2(*(__half2*)&ah3);
        unsigned al0 = pack_h2(x00.x - f0.x, x00.y - f0.y);
        unsigned al1 = pack_h2(x10.x - f1.x, x10.y - f1.y);
        unsigned al2 = pack_h2(x01.x - f2.x, x01.y - f2.y);
        unsigned al3 = pack_h2(x11.x - f3.x, x11.y - f3.y);

        #pragma unroll
        for (int nt = 0; nt < 8; nt++) {
            uint2 b = __ldg(Wbase + (nt * 4 + ks) * 32);
            mma_f16(acc[nt], ah0, ah1, ah2, ah3, b.x, b.y);
            mma_f16(acc[nt], al0, al1, al2, al3, b.x, b.y);
        }
    }

    int lr0 = wr + g, lr1 = lr0 + 8;

    if (cg == 0) {
        #pragma unroll
        for (int nt = 0; nt < 8; nt++) {
            int cl = nt * 8 + 2 * q;
            float b0 = __ldg(bl + cl), b1 = __ldg(bl + cl + 1);
            *(float2*)(buf + lr0 * EPS + cl) = make_float2(acc[nt][0] + b0, acc[nt][1] + b1);
            *(float2*)(buf + lr1 * EPS + cl) = make_float2(acc[nt][2] + b0, acc[nt][3] + b1);
        }
    }
    __syncthreads();
    for (int idx = tid; idx < 1024; idx += 256) {
        int row = idx >> 4, c4 = idx & 15;
        int gr = i0 + row;
        if (gr < n)
            *(float4*)(tmp + (size_t)gr * 64 + c4 * 4) = *(float4*)(buf + row * EPS + c4 * 4);
    }
    __syncthreads();

    unsigned* ubuf = (unsigned*)buf;
    if (cg == 1) {
        #pragma unroll
        for (int nt = 0; nt < 8; nt++) {
            int wi = nt * 4 + q;
            ubuf[lr0 * EPS + wi] = pack_h2(acc[nt][0], acc[nt][1]);
            ubuf[lr1 * EPS + wi] = pack_h2(acc[nt][2], acc[nt][3]);
        }
    }
    __syncthreads();
    for (int idx = tid; idx < 512; idx += 256) {
        int row = idx >> 3, c8 = idx & 7;
        int gr = i0 + row;
        if (gr < n)
            *(uint4*)(p + (size_t)gr * 64 + c8 * 8) = *(uint4*)(ubuf + row * EPS + c8 * 4);
    }
}

// ---------------- FUSED layer: h = relu(tmp + invdeg*gather(pin)) in smem, then GEMM ----------------
// Phase 1: each warp aggregates 8 rows into smem A (fp32, stride 72, conflict-free).
// Phase 2: GEMM from smem A (R11 layout), epilogue -> tmp (fp32+bias), pout (fp16).
#define FPS 72   // 72 % 32 = 8 -> fragment LDS.64 conflict-free; float4 stores aligned

__global__ void __launch_bounds__(256, 3) k_fmma(const __half* __restrict__ pin,
                                                 const uint2* __restrict__ Wf,
                                                 const float* __restrict__ bl,
                                                 float* __restrict__ tmp, __half* __restrict__ pout, int n) {
    __shared__ float buf[64 * FPS];
    int tid = threadIdx.x;
    int i0 = blockIdx.x * 64;
    int w = tid >> 5, lane = tid & 31;
    int half = lane >> 4, sub = lane & 15;
    const uint2* P2 = (const uint2*)pin;

    // ---- phase 1: aggregate 8 rows per warp into smem ----
    for (int j = 0; j < 8; j++) {
        int row = w * 8 + j, gr = i0 + row;
        float ax = 0.f, ay = 0.f, az = 0.f, aw = 0.f;
        float id = 1.f;
        if (gr < n) {
            int s = __ldg(g_rowptr + gr), eend = __ldg(g_rowptr + gr + 1);
            id = __ldg(g_invdeg + gr);
            int e = s;
            for (; e + 3 < eend; e += 4) {
                int q0 = __ldg(g_csrc + e + half);
                int q1 = __ldg(g_csrc + e + 2 + half);
                float4 u0 = h4_to_f4(__ldg(P2 + q0 * 16 + sub));
                float4 u1 = h4_to_f4(__ldg(P2 + q1 * 16 + sub));
                ax += u0.x + u1.x; ay += u0.y + u1.y;
                az += u0.z + u1.z; aw += u0.w + u1.w;
            }
            for (; e + 1 < eend; e += 2) {
                int q0 = __ldg(g_csrc + e + half);
                float4 u0 = h4_to_f4(__ldg(P2 + q0 * 16 + sub));
                ax += u0.x; ay += u0.y; az += u0.z; aw += u0.w;
            }
            if (e < eend && half == 0) {
                int q0 = __ldg(g_csrc + e);
                float4 u0 = h4_to_f4(__ldg(P2 + q0 * 16 + sub));
                ax += u0.x; ay += u0.y; az += u0.z; aw += u0.w;
            }
        }
        ax += __shfl_xor_sync(0xffffffffu, ax, 16);
        ay += __shfl_xor_sync(0xffffffffu, ay, 16);
        az += __shfl_xor_sync(0xffffffffu, az, 16);
        aw += __shfl_xor_sync(0xffffffffu, aw, 16);
        if (half == 0) {
            float4 t = (gr < n) ? __ldg((const float4*)tmp + gr * 16 + sub)
                                : make_float4(0.f, 0.f, 0.f, 0.f);
            float4 r;
            r.x = fmaxf(t.x + id * ax, 0.f);
            r.y = fmaxf(t.y + id * ay, 0.f);
            r.z = fmaxf(t.z + id * az, 0.f);
            r.w = fmaxf(t.w + id * aw, 0.f);
            *(float4*)(buf + row * FPS + sub * 4) = r;
        }
    }
    __syncthreads();

    // ---- phase 2: GEMM from smem A ----
    int wr = (w >> 1) * 16;
    int cg = w & 1;
    int g = lane >> 2, q = lane & 3;
    int lr0 = wr + g, lr1 = lr0 + 8;

    float acc[8][4];
    #pragma unroll
    for (int nt = 0; nt < 8; nt++)
        #pragma unroll
        for (int z = 0; z < 4; z++) acc[nt][z] = 0.f;

    const uint2* Wbase = Wf + cg * 1024 + lane;

    #pragma unroll
    for (int ks = 0; ks < 4; ks++) {
        int k0 = ks * 16 + 2 * q;
        float2 x00 = *(const float2*)(buf + lr0 * FPS + k0);
        float2 x10 = *(const float2*)(buf + lr1 * FPS + k0);
        float2 x01 = *(const float2*)(buf + lr0 * FPS + k0 + 8);
        float2 x11 = *(const float2*)(buf + lr1 * FPS + k0 + 8);

        unsigned ah0 = pack_h2(x00.x, x00.y);
        unsigned ah1 = pack_h2(x10.x, x10.y);
        unsigned ah2 = pack_h2(x01.x, x01.y);
        unsigned ah3 = pack_h2(x11.x, x11.y);
        float2 f0 = __half22float2(*(__half2*)&ah0);
        float2 f1 = __half22float2(*(__half2*)&ah1);
        float2 f2 = __half22float2(*(__half2*)&ah2);
        float2 f3 = __half22float2(*(__half2*)&ah3);
        unsigned al0 = pack_h2(x00.x - f0.x, x00.y - f0.y);
        unsigned al1 = pack_h2(x10.x - f1.x, x10.y - f1.y);
        unsigned al2 = pack_h2(x01.x - f2.x, x01.y - f2.y);
        unsigned al3 = pack_h2(x11.x - f3.x, x11.y - f3.y);

        #pragma unroll
        for (int nt = 0; nt < 8; nt++) {
            uint2 b = __ldg(Wbase + (nt * 4 + ks) * 32);
            mma_f16(acc[nt], ah0, ah1, ah2, ah3, b.x, b.y);
            mma_f16(acc[nt], al0, al1, al2, al3, b.x, b.y);
        }
    }
    __syncthreads();   // smem A fully consumed; reuse buffer for epilogue

    if (cg == 0) {
        #pragma unroll
        for (int nt = 0; nt < 8; nt++) {
            int cl = nt * 8 + 2 * q;
            float b0 = __ldg(bl + cl), b1 = __ldg(bl + cl + 1);
            *(float2*)(buf + lr0 * FPS + cl) = make_float2(acc[nt][0] + b0, acc[nt][1] + b1);
            *(float2*)(buf + lr1 * FPS + cl) = make_float2(acc[nt][2] + b0, acc[nt][3] + b1);
        }
    }
    __syncthreads();
    for (int idx = tid; idx < 1024; idx += 256) {
        int row = idx >> 4, c4 = idx & 15;
        int gr = i0 + row;
        if (gr < n)
            *(float4*)(tmp + (size_t)gr * 64 + c4 * 4) = *(float4*)(buf + row * FPS + c4 * 4);
    }
    __syncthreads();

    unsigned* ubuf = (unsigned*)buf;
    if (cg == 1) {
        #pragma unroll
        for (int nt = 0; nt < 8; nt++) {
            int wi = nt * 4 + q;
            ubuf[lr0 * FPS + wi] = pack_h2(acc[nt][0], acc[nt][1]);
            ubuf[lr1 * FPS + wi] = pack_h2(acc[nt][2], acc[nt][3]);
        }
    }
    __syncthreads();
    for (int idx = tid; idx < 512; idx += 256) {
        int row = idx >> 3, c8 = idx & 7;
        int gr = i0 + row;
        if (gr < n)
            *(uint4*)(pout + (size_t)gr * 64 + c8 * 8) = *(uint4*)(ubuf + row * FPS + c8 * 4);
    }
}

// ---------------- final: aggregation + classifier head ----------------
__global__ void k_aggr_out(const __half* __restrict__ p, const float* __restrict__ tmp,
                           const float* __restrict__ Wout, const float* __restrict__ bout,
                           float* __restrict__ out, int n) {
    int gw = (blockIdx.x * blockDim.x + threadIdx.x) >> 5;
    int lane = threadIdx.x & 31;
    if (gw >= n) return;
    int half = lane >> 4, sub = lane & 15;
    int s = __ldg(g_rowptr + gw), eend = __ldg(g_rowptr + gw + 1);
    const uint2* P2 = (const uint2*)p;
    float ax = 0.f, ay = 0.f, az = 0.f, aw = 0.f;
    int e = s;
    for (; e + 3 < eend; e += 4) {
        int r0 = __ldg(g_csrc + e + half);
        int r1 = __ldg(g_csrc + e + 2 + half);
        float4 u0 = h4_to_f4(__ldg(P2 + r0 * 16 + sub));
        float4 u1 = h4_to_f4(__ldg(P2 + r1 * 16 + sub));
        ax += u0.x + u1.x; ay += u0.y + u1.y;
        az += u0.z + u1.z; aw += u0.w + u1.w;
    }
    for (; e + 1 < eend; e += 2) {
        int r0 = __ldg(g_csrc + e + half);
        float4 u0 = h4_to_f4(__ldg(P2 + r0 * 16 + sub));
        ax += u0.x; ay += u0.y; az += u0.z; aw += u0.w;
    }
    if (e < eend && half == 0) {
        int r0 = __ldg(g_csrc + e);
        float4 u0 = h4_to_f4(__ldg(P2 + r0 * 16 + sub));
        ax += u0.x; ay += u0.y; az += u0.z; aw += u0.w;
    }
    ax += __shfl_xor_sync(0xffffffffu, ax, 16);
    ay += __shfl_xor_sync(0xffffffffu, ay, 16);
    az += __shfl_xor_sync(0xffffffffu, az, 16);
    aw += __shfl_xor_sync(0xffffffffu, aw, 16);

    float o0 = 0.f, o1 = 0.f;
    if (half == 0) {
        float id = __ldg(g_invdeg + gw);
        float4 t = __ldg((const float4*)tmp + gw * 16 + sub);
        float rx = t.x + id * ax, ry = t.y + id * ay;
        float rz = t.z + id * az, rw = t.w + id * aw;
        float4 w0 = __ldg((const float4*)Wout + sub);
        float4 w1 = __ldg((const float4*)(Wout + 64) + sub);
        o0 = rx * w0.x + ry * w0.y + rz * w0.z + rw * w0.w;
        o1 = rx * w1.x + ry * w1.y + rz * w1.z + rw * w1.w;
    }
    #pragma unroll
    for (int off = 8; off; off >>= 1) {
        o0 += __shfl_down_sync(0xffffffffu, o0, off);
        o1 += __shfl_down_sync(0xffffffffu, o1, off);
    }
    if (lane == 0) {
        out[gw * 2 + 0] = o0 + __ldg(bout + 0);
        out[gw * 2 + 1] = o1 + __ldg(bout + 1);
    }
}

// ---------------- launch ----------------
extern "C" void kernel_launch(void* const* d_in, const int* in_sizes, int n_in,
                              void* d_out, int out_size) {
    const float* x    = (const float*)d_in[0];
    const int*   ei   = (const int*)d_in[1];
    const float* Wl   = (const float*)d_in[2];
    const float* bl   = (const float*)d_in[3];
    const float* Wr   = (const float*)d_in[4];
    const float* Wout = (const float*)d_in[5];
    const float* bout = (const float*)d_in[6];
    float* out = (float*)d_out;

    int n = in_sizes[0] / DD;
    int e = in_sizes[1] / 2;
    const int* src = ei;
    const int* dst = ei + e;

    float* tP;
    __half *pA, *pB;
    uint2* WfP;
    int *degP, *curP;
    cudaGetSymbolAddress((void**)&pA, g_p);
    cudaGetSymbolAddress((void**)&pB, g_p2);
    cudaGetSymbolAddress((void**)&tP, g_tmp);
    cudaGetSymbolAddress((void**)&WfP, g_Wf);
    cudaGetSymbolAddress((void**)&degP, g_deg);
    cudaGetSymbolAddress((void**)&curP, g_cursor);

    int nb = (n + 1023) / 1024;
    int mma_blocks = (n + 63) / 64;
    int warp_blocks = (n + 7) / 8;

    cudaStream_t s1;
    cudaStreamCreateWithFlags(&s1, cudaStreamNonBlocking);
    cudaEvent_t evFork, evJoin;
    cudaEventCreateWithFlags(&evFork, cudaEventDisableTiming);
    cudaEventCreateWithFlags(&evJoin, cudaEventDisableTiming);

    // fork: side stream builds CSR while main stream does weights + layer-0 GEMM
    cudaEventRecord(evFork, 0);
    cudaStreamWaitEvent(s1, evFork, 0);

    cudaMemsetAsync(degP, 0, (size_t)n * sizeof(int), s1);
    cudaMemsetAsync(curP, 0, (size_t)n * sizeof(int), s1);
    k_prepW<<<(3 * 2048 + 255) / 256, 256>>>(Wr, Wl);                     // main
    k_count<<<(e + 255) / 256, 256, 0, s1>>>(dst, e);                     // side
    k_scanA<<<nb, 1024, 0, s1>>>(n);                                      // side
    k_mma<<<mma_blocks, 256>>>(x, WfP, bl, tP, pA, n);                    // main; ncu slot
    k_scanB<<<1, 128, 0, s1>>>(nb);                                       // side
    k_scanC<<<(n + 255) / 256, 256, 0, s1>>>(n, e);                       // side
    k_fill<<<(e + 255) / 256, 256, 0, s1>>>(src, dst, e);                 // side
    cudaEventRecord(evJoin, s1);

    // join: fused layers need CSR + layer-0 outputs
    cudaStreamWaitEvent(0, evJoin, 0);

    // fused layer 1: aggregate(pA) -> GEMM -> (tmp, pB)
    k_fmma<<<mma_blocks, 256>>>(pA, WfP + 2048, bl + 64, tP, pB, n);
    // fused layer 2: aggregate(pB) -> GEMM -> (tmp, pA)
    k_fmma<<<mma_blocks, 256>>>(pB, WfP + 4096, bl + 128, tP, pA, n);
    // final aggregation + head
    k_aggr_out<<<warp_blocks, 256>>>(pA, tP, Wout, bout, out, n);

    cudaEventDestroy(evFork);
    cudaEventDestroy(evJoin);
    cudaStreamDestroy(s1);
}

// round 16
// speedup vs baseline: 1.1249x; 1.1249x over previous
#include <cuda_runtime.h>
#include <cuda_bf16.h>
#include <cuda_fp16.h>
#include <cstdint>

#define NN 100000
#define EE 1000000
#define DD 64

// ---------------- device scratch ----------------
__device__ int      g_deg[NN];
__device__ int      g_cursor[NN];
__device__ int      g_rowptr[NN + 1];
__device__ int      g_bsum[128];
__device__ int      g_csrc[EE];
__device__ float    g_invdeg[NN];
__device__ float    g_h[NN * DD];
__device__ __half   g_p[NN * DD];      // fp16 lin_l partials, ping
__device__ __half   g_p2[NN * DD];     // fp16 lin_l partials, pong
__device__ float    g_tmp[NN * DD];
// W' fragment-major fp16: per layer 64 frag-groups x 32 lanes of uint2
__device__ uint2    g_Wf[3 * 2048];

__device__ __forceinline__ unsigned pack_h2(float a, float b) {
    __half2 t = __floats2half2_rn(a, b);
    return *(unsigned*)&t;
}
__device__ __forceinline__ float4 h4_to_f4(uint2 v) {
    float2 a = __half22float2(*(__half2*)&v.x);
    float2 b = __half22float2(*(__half2*)&v.y);
    return make_float4(a.x, a.y, b.x, b.y);
}

// ---------------- CSR construction ----------------
__global__ void k_count(const int* __restrict__ dst, int e) {
    int i = blockIdx.x * blockDim.x + threadIdx.x;
    if (i < e) atomicAdd(&g_deg[__ldg(dst + i)], 1);
}

__global__ void k_scanA(int n) {
    __shared__ int wsum[32];
    int t = threadIdx.x;
    int i = blockIdx.x * 1024 + t;
    int v = (i < n) ? g_deg[i] : 0;
    int lane = t & 31, w = t >> 5;
    int s = v;
    #pragma unroll
    for (int off = 1; off < 32; off <<= 1) {
        int u = __shfl_up_sync(0xffffffffu, s, off);
        if (lane >= off) s += u;
    }
    if (lane == 31) wsum[w] = s;
    __syncthreads();
    if (w == 0) {
        int ws = wsum[lane];
        #pragma unroll
        for (int off = 1; off < 32; off <<= 1) {
            int u = __shfl_up_sync(0xffffffffu, ws, off);
            if (lane >= off) ws += u;
        }
        wsum[lane] = ws;
    }
    __syncthreads();
    int base = (w > 0) ? wsum[w - 1] : 0;
    int incl = base + s;
    if (i < n) g_rowptr[i] = incl - v;          // exclusive
    if (t == 1023) g_bsum[blockIdx.x] = incl;
}

__global__ void k_scanB(int nb) {
    __shared__ int wsum[4];
    int t = threadIdx.x;                        // 128 threads
    int lane = t & 31, w = t >> 5;
    int v = (t < nb) ? g_bsum[t] : 0;
    int s = v;
    #pragma unroll
    for (int off = 1; off < 32; off <<= 1) {
        int u = __shfl_up_sync(0xffffffffu, s, off);
        if (lane >= off) s += u;
    }
    if (lane == 31) wsum[w] = s;
    __syncthreads();
    int base = 0;
    for (int q = 0; q < w; q++) base += wsum[q];
    if (t < nb) g_bsum[t] = base + s - v;       // exclusive
}

__global__ void k_scanC(int n, int e) {
    int i = blockIdx.x * blockDim.x + threadIdx.x;
    if (i < n) {
        g_rowptr[i] += g_bsum[i >> 10];
        g_invdeg[i] = 1.0f / fmaxf((float)g_deg[i], 1.0f);
    }
    if (i == 0) g_rowptr[n] = e;
}

__global__ void k_fill(const int* __restrict__ src, const int* __restrict__ dst, int e) {
    int i = blockIdx.x * blockDim.x + threadIdx.x;
    if (i < e) {
        int d = __ldg(dst + i);
        int pos = g_rowptr[d] + atomicAdd(&g_cursor[d], 1);
        g_csrc[pos] = __ldg(src + i);
    }
}

// ---------------- W' precompute into fragment-major fp16 layout ----------------
__global__ void k_prepW(const float* __restrict__ Wr, const float* __restrict__ Wl) {
    int idx = blockIdx.x * blockDim.x + threadIdx.x;
    if (idx >= 3 * 2048) return;
    int l = idx / 2048;
    int rem = idx - l * 2048;
    int fg = rem >> 5;
    int lane = rem & 31;
    int cg = fg >> 5;
    int nt = (fg >> 2) & 7;
    int ks = fg & 3;
    int c = cg * 64 + nt * 8 + (lane >> 2);
    int q = lane & 3;
    int k0 = 16 * ks + 2 * q;
    int k1 = k0 + 8;
    const float* Wsrc = (c < 64) ? (Wr + l * 4096 + c * 64) : (Wl + l * 4096 + (c - 64) * 64);
    uint2 v;
    v.x = pack_h2(__ldg(Wsrc + k0), __ldg(Wsrc + k0 + 1));
    v.y = pack_h2(__ldg(Wsrc + k1), __ldg(Wsrc + k1 + 1));
    g_Wf[idx] = v;
}

__device__ __forceinline__ void mma_f16(float* c, unsigned a0, unsigned a1, unsigned a2,
                                        unsigned a3, unsigned b0, unsigned b1) {
    asm volatile(
        "mma.sync.aligned.m16n8k16.row.col.f32.f16.f16.f32 "
        "{%0,%1,%2,%3}, {%4,%5,%6,%7}, {%8,%9}, {%0,%1,%2,%3};"
        : "+f"(c[0]), "+f"(c[1]), "+f"(c[2]), "+f"(c[3])
        : "r"(a0), "r"(a1), "r"(a2), "r"(a3), "r"(b0), "r"(b1));
}

// ---------------- HMMA dual GEMM (R12 config + row offset): tmp = A@Wr^T + bl ; p = A@Wl^T ----------------
#define EPS 68

__global__ void __launch_bounds__(256, 3) k_mma(const float* __restrict__ A,
                                                const uint2* __restrict__ Wf,
                                                const float* __restrict__ bl,
                                                float* __restrict__ tmp, __half* __restrict__ p,
                                                int n, int row0) {
    __shared__ float buf[64 * EPS];
    int tid = threadIdx.x;
    int i0 = row0 + blockIdx.x * 64;

    int w = tid >> 5, lane = tid & 31;
    int wr = (w >> 1) * 16;
    int cg = w & 1;
    int g = lane >> 2, q = lane & 3;

    int r0 = i0 + wr + g, r1 = r0 + 8;
    bool v0 = r0 < n, v1 = r1 < n;
    const float* A0 = A + (size_t)r0 * 64;
    const float* A1 = A + (size_t)r1 * 64;

    float acc[8][4];
    #pragma unroll
    for (int nt = 0; nt < 8; nt++)
        #pragma unroll
        for (int z = 0; z < 4; z++) acc[nt][z] = 0.f;

    const uint2* Wbase = Wf + cg * 1024 + lane;

    #pragma unroll
    for (int ks = 0; ks < 4; ks++) {
        int k0 = ks * 16 + 2 * q;
        float2 z = make_float2(0.f, 0.f);
        float2 x00 = v0 ? __ldg((const float2*)(A0 + k0))     : z;
        float2 x10 = v1 ? __ldg((const float2*)(A1 + k0))     : z;
        float2 x01 = v0 ? __ldg((const float2*)(A0 + k0 + 8)) : z;
        float2 x11 = v1 ? __ldg((const float2*)(A1 + k0 + 8)) : z;

        unsigned ah0 = pack_h2(x00.x, x00.y);
        unsigned ah1 = pack_h2(x10.x, x10.y);
        unsigned ah2 = pack_h2(x01.x, x01.y);
        unsigned ah3 = pack_h2(x11.x, x11.y);
        float2 f0 = __half22float2(*(__half2*)&ah0);
        float2 f1 = __half22float2(*(__half2*)&ah1);
        float2 f2 = __half22float2(*(__half2*)&ah2);
        float2 f3 = __half22float2(*(__half2*)&ah3);
        unsigned al0 = pack_h2(x00.x - f0.x, x00.y - f0.y);
        unsigned al1 = pack_h2(x10.x - f1.x, x10.y - f1.y);
        unsigned al2 = pack_h2(x01.x - f2.x, x01.y - f2.y);
        unsigned al3 = pack_h2(x11.x - f3.x, x11.y - f3.y);

        #pragma unroll
        for (int nt = 0; nt < 8; nt++) {
            uint2 b = __ldg(Wbase + (nt * 4 + ks) * 32);
            mma_f16(acc[nt], ah0, ah1, ah2, ah3, b.x, b.y);
            mma_f16(acc[nt], al0, al1, al2, al3, b.x, b.y);
        }
    }

    int lr0 = wr + g, lr1 = lr0 + 8;

    if (cg == 0) {
        #pragma unroll
        for (int nt = 0; nt < 8; nt++) {
            int cl = nt * 8 + 2 * q;
            float b0 = __ldg(bl + cl), b1 = __ldg(bl + cl + 1);
            *(float2*)(buf + lr0 * EPS + cl) = make_float2(acc[nt][0] + b0, acc[nt][1] + b1);
            *(float2*)(buf + lr1 * EPS + cl) = make_float2(acc[nt][2] + b0, acc[nt][3] + b1);
        }
    }
    __syncthreads();
    for (int idx = tid; idx < 1024; idx += 256) {
        int row = idx >> 4, c4 = idx & 15;
        int gr = i0 + row;
        if (gr < n)
            *(float4*)(tmp + (size_t)gr * 64 + c4 * 4) = *(float4*)(buf + row * EPS + c4 * 4);
    }
    __syncthreads();

    unsigned* ubuf = (unsigned*)buf;
    if (cg == 1) {
        #pragma unroll
        for (int nt = 0; nt < 8; nt++) {
            int wi = nt * 4 + q;
            ubuf[lr0 * EPS + wi] = pack_h2(acc[nt][0], acc[nt][1]);
            ubuf[lr1 * EPS + wi] = pack_h2(acc[nt][2], acc[nt][3]);
        }
    }
    __syncthreads();
    for (int idx = tid; idx < 512; idx += 256) {
        int row = idx >> 3, c8 = idx & 7;
        int gr = i0 + row;
        if (gr < n)
            *(uint4*)(p + (size_t)gr * 64 + c8 * 8) = *(uint4*)(ubuf + row * EPS + c8 * 4);
    }
}

// ---------------- aggregation (R14, chunked): h[i] = relu(tmp[i] + invdeg[i]*sum p[src]) ----------------
__global__ void k_aggr(const __half* __restrict__ p, const float* __restrict__ tmp,
                       float* __restrict__ h, int base, int end) {
    int gw = base + ((blockIdx.x * blockDim.x + threadIdx.x) >> 5);
    int lane = threadIdx.x & 31;
    if (gw >= end) return;
    int half = lane >> 4, sub = lane & 15;
    int s = __ldg(g_rowptr + gw), eend = __ldg(g_rowptr + gw + 1);
    const uint2* P2 = (const uint2*)p;
    float ax = 0.f, ay = 0.f, az = 0.f, aw = 0.f;
    int e = s;
    for (; e + 3 < eend; e += 4) {
        int r0 = __ldg(g_csrc + e + half);
        int r1 = __ldg(g_csrc + e + 2 + half);
        float4 u0 = h4_to_f4(__ldg(P2 + r0 * 16 + sub));
        float4 u1 = h4_to_f4(__ldg(P2 + r1 * 16 + sub));
        ax += u0.x + u1.x; ay += u0.y + u1.y;
        az += u0.z + u1.z; aw += u0.w + u1.w;
    }
    for (; e + 1 < eend; e += 2) {
        int r0 = __ldg(g_csrc + e + half);
        float4 u0 = h4_to_f4(__ldg(P2 + r0 * 16 + sub));
        ax += u0.x; ay += u0.y; az += u0.z; aw += u0.w;
    }
    if (e < eend && half == 0) {
        int r0 = __ldg(g_csrc + e);
        float4 u0 = h4_to_f4(__ldg(P2 + r0 * 16 + sub));
        ax += u0.x; ay += u0.y; az += u0.z; aw += u0.w;
    }
    ax += __shfl_xor_sync(0xffffffffu, ax, 16);
    ay += __shfl_xor_sync(0xffffffffu, ay, 16);
    az += __shfl_xor_sync(0xffffffffu, az, 16);
    aw += __shfl_xor_sync(0xffffffffu, aw, 16);
    if (half == 0) {
        float id = __ldg(g_invdeg + gw);
        float4 t = __ldg((const float4*)tmp + gw * 16 + sub);
        float4 r;
        r.x = fmaxf(t.x + id * ax, 0.f);
        r.y = fmaxf(t.y + id * ay, 0.f);
        r.z = fmaxf(t.z + id * az, 0.f);
        r.w = fmaxf(t.w + id * aw, 0.f);
        ((float4*)h)[gw * 16 + sub] = r;
    }
}

// ---------------- final: aggregation + classifier head (R14) ----------------
__global__ void k_aggr_out(const __half* __restrict__ p, const float* __restrict__ tmp,
                           const float* __restrict__ Wout, const float* __restrict__ bout,
                           float* __restrict__ out, int n) {
    int gw = (blockIdx.x * blockDim.x + threadIdx.x) >> 5;
    int lane = threadIdx.x & 31;
    if (gw >= n) return;
    int half = lane >> 4, sub = lane & 15;
    int s = __ldg(g_rowptr + gw), eend = __ldg(g_rowptr + gw + 1);
    const uint2* P2 = (const uint2*)p;
    float ax = 0.f, ay = 0.f, az = 0.f, aw = 0.f;
    int e = s;
    for (; e + 3 < eend; e += 4) {
        int r0 = __ldg(g_csrc + e + half);
        int r1 = __ldg(g_csrc + e + 2 + half);
        float4 u0 = h4_to_f4(__ldg(P2 + r0 * 16 + sub));
        float4 u1 = h4_to_f4(__ldg(P2 + r1 * 16 + sub));
        ax += u0.x + u1.x; ay += u0.y + u1.y;
        az += u0.z + u1.z; aw += u0.w + u1.w;
    }
    for (; e + 1 < eend; e += 2) {
        int r0 = __ldg(g_csrc + e + half);
        float4 u0 = h4_to_f4(__ldg(P2 + r0 * 16 + sub));
        ax += u0.x; ay += u0.y; az += u0.z; aw += u0.w;
    }
    if (e < eend && half == 0) {
        int r0 = __ldg(g_csrc + e);
        float4 u0 = h4_to_f4(__ldg(P2 + r0 * 16 + sub));
        ax += u0.x; ay += u0.y; az += u0.z; aw += u0.w;
    }
    ax += __shfl_xor_sync(0xffffffffu, ax, 16);
    ay += __shfl_xor_sync(0xffffffffu, ay, 16);
    az += __shfl_xor_sync(0xffffffffu, az, 16);
    aw += __shfl_xor_sync(0xffffffffu, aw, 16);

    float o0 = 0.f, o1 = 0.f;
    if (half == 0) {
        float id = __ldg(g_invdeg + gw);
        float4 t = __ldg((const float4*)tmp + gw * 16 + sub);
        float rx = t.x + id * ax, ry = t.y + id * ay;
        float rz = t.z + id * az, rw = t.w + id * aw;
        float4 w0 = __ldg((const float4*)Wout + sub);
        float4 w1 = __ldg((const float4*)(Wout + 64) + sub);
        o0 = rx * w0.x + ry * w0.y + rz * w0.z + rw * w0.w;
        o1 = rx * w1.x + ry * w1.y + rz * w1.z + rw * w1.w;
    }
    #pragma unroll
    for (int off = 8; off; off >>= 1) {
        o0 += __shfl_down_sync(0xffffffffu, o0, off);
        o1 += __shfl_down_sync(0xffffffffu, o1, off);
    }
    if (lane == 0) {
        out[gw * 2 + 0] = o0 + __ldg(bout + 0);
        out[gw * 2 + 1] = o1 + __ldg(bout + 1);
    }
}

// ---------------- launch: CSR/GEMM fork-join + per-layer chunk pipelining ----------------
extern "C" void kernel_launch(void* const* d_in, const int* in_sizes, int n_in,
                              void* d_out, int out_size) {
    const float* x    = (const float*)d_in[0];
    const int*   ei   = (const int*)d_in[1];
    const float* Wl   = (const float*)d_in[2];
    const float* bl   = (const float*)d_in[3];
    const float* Wr   = (const float*)d_in[4];
    const float* Wout = (const float*)d_in[5];
    const float* bout = (const float*)d_in[6];
    float* out = (float*)d_out;

    int n = in_sizes[0] / DD;
    int e = in_sizes[1] / 2;
    const int* src = ei;
    const int* dst = ei + e;

    float *hP, *tP;
    __half *pA, *pB;
    uint2* WfP;
    int *degP, *curP;
    cudaGetSymbolAddress((void**)&hP, g_h);
    cudaGetSymbolAddress((void**)&pA, g_p);
    cudaGetSymbolAddress((void**)&pB, g_p2);
    cudaGetSymbolAddress((void**)&tP, g_tmp);
    cudaGetSymbolAddress((void**)&WfP, g_Wf);
    cudaGetSymbolAddress((void**)&degP, g_deg);
    cudaGetSymbolAddress((void**)&curP, g_cursor);

    int nb = (n + 1023) / 1024;
    int mma_blocks = (n + 63) / 64;

    // chunk split on a 64-row boundary (~60/40 toward chunk0 to balance mma0 vs aggr1)
    int n2 = ((n * 3 / 5 + 63) / 64) * 64;
    if (n2 > n) n2 = n;
    int mma_b0 = n2 / 64;
    int mma_b1 = (n - n2 + 63) / 64;
    int wb0 = (n2 + 7) / 8;
    int wb1 = (n - n2 + 7) / 8;
    int wb_all = (n + 7) / 8;

    cudaStream_t s1;
    cudaStreamCreateWithFlags(&s1, cudaStreamNonBlocking);
    cudaEvent_t evFork, evJoin, evA1, evL1, evA2, evL2;
    cudaEventCreateWithFlags(&evFork, cudaEventDisableTiming);
    cudaEventCreateWithFlags(&evJoin, cudaEventDisableTiming);
    cudaEventCreateWithFlags(&evA1, cudaEventDisableTiming);
    cudaEventCreateWithFlags(&evL1, cudaEventDisableTiming);
    cudaEventCreateWithFlags(&evA2, cudaEventDisableTiming);
    cudaEventCreateWithFlags(&evL2, cudaEventDisableTiming);

    // ---- fork: side stream builds CSR while main does weights + layer-0 GEMM ----
    cudaEventRecord(evFork, 0);
    cudaStreamWaitEvent(s1, evFork, 0);

    cudaMemsetAsync(degP, 0, (size_t)n * sizeof(int), s1);
    cudaMemsetAsync(curP, 0, (size_t)n * sizeof(int), s1);
    k_prepW<<<(3 * 2048 + 255) / 256, 256>>>(Wr, Wl);                     // main
    k_count<<<(e + 255) / 256, 256, 0, s1>>>(dst, e);                     // side
    k_scanA<<<nb, 1024, 0, s1>>>(n);                                      // side
    k_mma<<<mma_blocks, 256>>>(x, WfP, bl, tP, pA, n, 0);                 // main; ncu slot
    k_scanB<<<1, 128, 0, s1>>>(nb);                                       // side
    k_scanC<<<(n + 255) / 256, 256, 0, s1>>>(n, e);                       // side
    k_fill<<<(e + 255) / 256, 256, 0, s1>>>(src, dst, e);                 // side
    cudaEventRecord(evJoin, s1);
    cudaStreamWaitEvent(0, evJoin, 0);

    // ---- layer 1 (reads pA, writes pB), pipelined across 2 node chunks ----
    k_aggr<<<wb0, 256>>>(pA, tP, hP, 0, n2);                              // main: aggr c0
    cudaEventRecord(evA1, 0);
    k_mma<<<mma_b0, 256>>>(hP, WfP + 2048, bl + 64, tP, pB, n, 0);        // main: mma c0
    cudaStreamWaitEvent(s1, evA1, 0);                                     // skew
    k_aggr<<<wb1, 256, 0, s1>>>(pA, tP, hP, n2, n);                       // side: aggr c1 (|| mma c0)
    k_mma<<<mma_b1, 256, 0, s1>>>(hP, WfP + 2048, bl + 64, tP, pB, n, n2);// side: mma c1
    cudaEventRecord(evL1, s1);
    cudaStreamWaitEvent(0, evL1, 0);

    // ---- layer 2 (reads pB, writes pA), same pipeline ----
    k_aggr<<<wb0, 256>>>(pB, tP, hP, 0, n2);
    cudaEventRecord(evA2, 0);
    k_mma<<<mma_b0, 256>>>(hP, WfP + 4096, bl + 128, tP, pA, n, 0);
    cudaStreamWaitEvent(s1, evA2, 0);
    k_aggr<<<wb1, 256, 0, s1>>>(pB, tP, hP, n2, n);
    k_mma<<<mma_b1, 256, 0, s1>>>(hP, WfP + 4096, bl + 128, tP, pA, n, n2);
    cudaEventRecord(evL2, s1);
    cudaStreamWaitEvent(0, evL2, 0);

    // ---- final aggregation + classifier head ----
    k_aggr_out<<<wb_all, 256>>>(pA, tP, Wout, bout, out, n);

    cudaEventDestroy(evFork);
    cudaEventDestroy(evJoin);
    cudaEventDestroy(evA1);
    cudaEventDestroy(evL1);
    cudaEventDestroy(evA2);
    cudaEventDestroy(evL2);
    cudaStreamDestroy(s1);
}

// round 17
// speedup vs baseline: 1.1812x; 1.0501x over previous
#include <cuda_runtime.h>
#include <cuda_bf16.h>
#include <cuda_fp16.h>
#include <cstdint>

#define NN 100000
#define EE 1000000
#define DD 64

// ---------------- device scratch ----------------
__device__ int      g_deg[NN];
__device__ int      g_cursor[NN];
__device__ int      g_rowptr[NN + 1];
__device__ int      g_bsum[128];
__device__ int      g_csrc[EE];
__device__ float    g_invdeg[NN];
__device__ float    g_h[NN * DD];
__device__ __half   g_p[NN * DD];      // fp16: gathered lin_l partials
__device__ float    g_tmp[NN * DD];
// W' fragment-major fp16: per layer 64 frag-groups x 32 lanes of uint2
__device__ uint2    g_Wf[3 * 2048];

__device__ __forceinline__ unsigned pack_h2(float a, float b) {
    __half2 t = __floats2half2_rn(a, b);
    return *(unsigned*)&t;
}

// accumulate 8 halves (uint4) into 8 float accumulators
__device__ __forceinline__ void acc8(float* a, uint4 v) {
    float2 f0 = __half22float2(*(__half2*)&v.x);
    float2 f1 = __half22float2(*(__half2*)&v.y);
    float2 f2 = __half22float2(*(__half2*)&v.z);
    float2 f3 = __half22float2(*(__half2*)&v.w);
    a[0] += f0.x; a[1] += f0.y; a[2] += f1.x; a[3] += f1.y;
    a[4] += f2.x; a[5] += f2.y; a[6] += f3.x; a[7] += f3.y;
}

// ---------------- CSR construction ----------------
__global__ void k_count(const int* __restrict__ dst, int e) {
    int i = blockIdx.x * blockDim.x + threadIdx.x;
    if (i < e) atomicAdd(&g_deg[__ldg(dst + i)], 1);
}

__global__ void k_scanA(int n) {
    __shared__ int wsum[32];
    int t = threadIdx.x;
    int i = blockIdx.x * 1024 + t;
    int v = (i < n) ? g_deg[i] : 0;
    int lane = t & 31, w = t >> 5;
    int s = v;
    #pragma unroll
    for (int off = 1; off < 32; off <<= 1) {
        int u = __shfl_up_sync(0xffffffffu, s, off);
        if (lane >= off) s += u;
    }
    if (lane == 31) wsum[w] = s;
    __syncthreads();
    if (w == 0) {
        int ws = wsum[lane];
        #pragma unroll
        for (int off = 1; off < 32; off <<= 1) {
            int u = __shfl_up_sync(0xffffffffu, ws, off);
            if (lane >= off) ws += u;
        }
        wsum[lane] = ws;
    }
    __syncthreads();
    int base = (w > 0) ? wsum[w - 1] : 0;
    int incl = base + s;
    if (i < n) g_rowptr[i] = incl - v;          // exclusive
    if (t == 1023) g_bsum[blockIdx.x] = incl;
}

__global__ void k_scanB(int nb) {
    __shared__ int wsum[4];
    int t = threadIdx.x;                        // 128 threads
    int lane = t & 31, w = t >> 5;
    int v = (t < nb) ? g_bsum[t] : 0;
    int s = v;
    #pragma unroll
    for (int off = 1; off < 32; off <<= 1) {
        int u = __shfl_up_sync(0xffffffffu, s, off);
        if (lane >= off) s += u;
    }
    if (lane == 31) wsum[w] = s;
    __syncthreads();
    int base = 0;
    for (int q = 0; q < w; q++) base += wsum[q];
    if (t < nb) g_bsum[t] = base + s - v;       // exclusive
}

__global__ void k_scanC(int n, int e) {
    int i = blockIdx.x * blockDim.x + threadIdx.x;
    if (i < n) {
        g_rowptr[i] += g_bsum[i >> 10];
        g_invdeg[i] = 1.0f / fmaxf((float)g_deg[i], 1.0f);
    }
    if (i == 0) g_rowptr[n] = e;
}

__global__ void k_fill(const int* __restrict__ src, const int* __restrict__ dst, int e) {
    int i = blockIdx.x * blockDim.x + threadIdx.x;
    if (i < e) {
        int d = __ldg(dst + i);
        int pos = g_rowptr[d] + atomicAdd(&g_cursor[d], 1);
        g_csrc[pos] = __ldg(src + i);
    }
}

// ---------------- W' precompute into fragment-major fp16 layout ----------------
__global__ void k_prepW(const float* __restrict__ Wr, const float* __restrict__ Wl) {
    int idx = blockIdx.x * blockDim.x + threadIdx.x;
    if (idx >= 3 * 2048) return;
    int l = idx / 2048;
    int rem = idx - l * 2048;
    int fg = rem >> 5;
    int lane = rem & 31;
    int cg = fg >> 5;
    int nt = (fg >> 2) & 7;
    int ks = fg & 3;
    int c = cg * 64 + nt * 8 + (lane >> 2);
    int q = lane & 3;
    int k0 = 16 * ks + 2 * q;
    int k1 = k0 + 8;
    const float* Wsrc = (c < 64) ? (Wr + l * 4096 + c * 64) : (Wl + l * 4096 + (c - 64) * 64);
    uint2 v;
    v.x = pack_h2(__ldg(Wsrc + k0), __ldg(Wsrc + k0 + 1));
    v.y = pack_h2(__ldg(Wsrc + k1), __ldg(Wsrc + k1 + 1));
    g_Wf[idx] = v;
}

__device__ __forceinline__ void mma_f16(float* c, unsigned a0, unsigned a1, unsigned a2,
                                        unsigned a3, unsigned b0, unsigned b1) {
    asm volatile(
        "mma.sync.aligned.m16n8k16.row.col.f32.f16.f16.f32 "
        "{%0,%1,%2,%3}, {%4,%5,%6,%7}, {%8,%9}, {%0,%1,%2,%3};"
        : "+f"(c[0]), "+f"(c[1]), "+f"(c[2]), "+f"(c[3])
        : "r"(a0), "r"(a1), "r"(a2), "r"(a3), "r"(b0), "r"(b1));
}

// ---------------- HMMA dual GEMM (R12 config): tmp = A@Wr^T + bl ; p = A@Wl^T ----------------
#define EPS 68

__global__ void __launch_bounds__(256, 3) k_mma(const float* __restrict__ A,
                                                const uint2* __restrict__ Wf,
                                                const float* __restrict__ bl,
                                                float* __restrict__ tmp, __half* __restrict__ p, int n) {
    __shared__ float buf[64 * EPS];
    int tid = threadIdx.x;
    int i0 = blockIdx.x * 64;

    int w = tid >> 5, lane = tid & 31;
    int wr = (w >> 1) * 16;
    int cg = w & 1;
    int g = lane >> 2, q = lane & 3;

    int r0 = i0 + wr + g, r1 = r0 + 8;
    bool v0 = r0 < n, v1 = r1 < n;
    const float* A0 = A + (size_t)r0 * 64;
    const float* A1 = A + (size_t)r1 * 64;

    float acc[8][4];
    #pragma unroll
    for (int nt = 0; nt < 8; nt++)
        #pragma unroll
        for (int z = 0; z < 4; z++) acc[nt][z] = 0.f;

    const uint2* Wbase = Wf + cg * 1024 + lane;

    #pragma unroll
    for (int ks = 0; ks < 4; ks++) {
        int k0 = ks * 16 + 2 * q;
        float2 z = make_float2(0.f, 0.f);
        float2 x00 = v0 ? __ldg((const float2*)(A0 + k0))     : z;
        float2 x10 = v1 ? __ldg((const float2*)(A1 + k0))     : z;
        float2 x01 = v0 ? __ldg((const float2*)(A0 + k0 + 8)) : z;
        float2 x11 = v1 ? __ldg((const float2*)(A1 + k0 + 8)) : z;

        unsigned ah0 = pack_h2(x00.x, x00.y);
        unsigned ah1 = pack_h2(x10.x, x10.y);
        unsigned ah2 = pack_h2(x01.x, x01.y);
        unsigned ah3 = pack_h2(x11.x, x11.y);
        float2 f0 = __half22float2(*(__half2*)&ah0);
        float2 f1 = __half22float2(*(__half2*)&ah1);
        float2 f2 = __half22float2(*(__half2*)&ah2);
        float2 f3 = __half22float2(*(__half2*)&ah3);
        unsigned al0 = pack_h2(x00.x - f0.x, x00.y - f0.y);
        unsigned al1 = pack_h2(x10.x - f1.x, x10.y - f1.y);
        unsigned al2 = pack_h2(x01.x - f2.x, x01.y - f2.y);
        unsigned al3 = pack_h2(x11.x - f3.x, x11.y - f3.y);

        #pragma unroll
        for (int nt = 0; nt < 8; nt++) {
            uint2 b = __ldg(Wbase + (nt * 4 + ks) * 32);
            mma_f16(acc[nt], ah0, ah1, ah2, ah3, b.x, b.y);
            mma_f16(acc[nt], al0, al1, al2, al3, b.x, b.y);
        }
    }

    int lr0 = wr + g, lr1 = lr0 + 8;

    if (cg == 0) {
        #pragma unroll
        for (int nt = 0; nt < 8; nt++) {
            int cl = nt * 8 + 2 * q;
            float b0 = __ldg(bl + cl), b1 = __ldg(bl + cl + 1);
            *(float2*)(buf + lr0 * EPS + cl) = make_float2(acc[nt][0] + b0, acc[nt][1] + b1);
            *(float2*)(buf + lr1 * EPS + cl) = make_float2(acc[nt][2] + b0, acc[nt][3] + b1);
        }
    }
    __syncthreads();
    for (int idx = tid; idx < 1024; idx += 256) {
        int row = idx >> 4, c4 = idx & 15;
        int gr = i0 + row;
        if (gr < n)
            *(float4*)(tmp + (size_t)gr * 64 + c4 * 4) = *(float4*)(buf + row * EPS + c4 * 4);
    }
    __syncthreads();

    unsigned* ubuf = (unsigned*)buf;
    if (cg == 1) {
        #pragma unroll
        for (int nt = 0; nt < 8; nt++) {
            int wi = nt * 4 + q;
            ubuf[lr0 * EPS + wi] = pack_h2(acc[nt][0], acc[nt][1]);
            ubuf[lr1 * EPS + wi] = pack_h2(acc[nt][2], acc[nt][3]);
        }
    }
    __syncthreads();
    for (int idx = tid; idx < 512; idx += 256) {
        int row = idx >> 3, c8 = idx & 7;
        int gr = i0 + row;
        if (gr < n)
            *(uint4*)(p + (size_t)gr * 64 + c8 * 8) = *(uint4*)(ubuf + row * EPS + c8 * 4);
    }
}

// ---------------- aggregation (quarter-warp): 4 edges per gather instruction ----------------
// Warp = 1 node. quarter (lane>>3) selects edge within group of 4; sub (lane&7)
// covers 8 uint4 (16B each, 8x16 = full 128B row). Reduce via shfl_xor(8) + shfl_xor(16).
__global__ void k_aggr(const __half* __restrict__ p, const float* __restrict__ tmp,
                       float* __restrict__ h, int n) {
    int gw = (blockIdx.x * blockDim.x + threadIdx.x) >> 5;
    int lane = threadIdx.x & 31;
    if (gw >= n) return;
    int quarter = lane >> 3, sub = lane & 7;
    int s = __ldg(g_rowptr + gw), eend = __ldg(g_rowptr + gw + 1);
    const uint4* P4 = (const uint4*)p;        // row stride 8 uint4
    float a[8];
    #pragma unroll
    for (int i = 0; i < 8; i++) a[i] = 0.f;
    int e = s;
    for (; e + 7 < eend; e += 8) {            // 8 edges: 2 quad-gathers in flight
        int r0 = __ldg(g_csrc + e + quarter);
        int r1 = __ldg(g_csrc + e + 4 + quarter);
        uint4 u0 = __ldg(P4 + r0 * 8 + sub);
        uint4 u1 = __ldg(P4 + r1 * 8 + sub);
        acc8(a, u0);
        acc8(a, u1);
    }
    for (; e + 3 < eend; e += 4) {            // one quad
        int r0 = __ldg(g_csrc + e + quarter);
        acc8(a, __ldg(P4 + r0 * 8 + sub));
    }
    int rem = eend - e;                       // 0..3 leftover edges
    if (quarter < rem) {
        int r0 = __ldg(g_csrc + e + quarter);
        acc8(a, __ldg(P4 + r0 * 8 + sub));
    }
    // reduce the 4 quarters (column sets identical across quarters)
    #pragma unroll
    for (int i = 0; i < 8; i++) {
        a[i] += __shfl_xor_sync(0xffffffffu, a[i], 8);
        a[i] += __shfl_xor_sync(0xffffffffu, a[i], 16);
    }
    if (quarter == 0) {
        float id = __ldg(g_invdeg + gw);
        float4 t0 = __ldg((const float4*)tmp + gw * 16 + sub * 2);
        float4 t1 = __ldg((const float4*)tmp + gw * 16 + sub * 2 + 1);
        float4 r0, r1;
        r0.x = fmaxf(t0.x + id * a[0], 0.f);
        r0.y = fmaxf(t0.y + id * a[1], 0.f);
        r0.z = fmaxf(t0.z + id * a[2], 0.f);
        r0.w = fmaxf(t0.w + id * a[3], 0.f);
        r1.x = fmaxf(t1.x + id * a[4], 0.f);
        r1.y = fmaxf(t1.y + id * a[5], 0.f);
        r1.z = fmaxf(t1.z + id * a[6], 0.f);
        r1.w = fmaxf(t1.w + id * a[7], 0.f);
        ((float4*)h)[gw * 16 + sub * 2]     = r0;
        ((float4*)h)[gw * 16 + sub * 2 + 1] = r1;
    }
}

// ---------------- final layer: quarter-warp aggregation fused with classifier head ----------------
__global__ void k_aggr_out(const __half* __restrict__ p, const float* __restrict__ tmp,
                           const float* __restrict__ Wout, const float* __restrict__ bout,
                           float* __restrict__ out, int n) {
    int gw = (blockIdx.x * blockDim.x + threadIdx.x) >> 5;
    int lane = threadIdx.x & 31;
    if (gw >= n) return;
    int quarter = lane >> 3, sub = lane & 7;
    int s = __ldg(g_rowptr + gw), eend = __ldg(g_rowptr + gw + 1);
    const uint4* P4 = (const uint4*)p;
    float a[8];
    #pragma unroll
    for (int i = 0; i < 8; i++) a[i] = 0.f;
    int e = s;
    for (; e + 7 < eend; e += 8) {
        int r0 = __ldg(g_csrc + e + quarter);
        int r1 = __ldg(g_csrc + e + 4 + quarter);
        uint4 u0 = __ldg(P4 + r0 * 8 + sub);
        uint4 u1 = __ldg(P4 + r1 * 8 + sub);
        acc8(a, u0);
        acc8(a, u1);
    }
    for (; e + 3 < eend; e += 4) {
        int r0 = __ldg(g_csrc + e + quarter);
        acc8(a, __ldg(P4 + r0 * 8 + sub));
    }
    int rem = eend - e;
    if (quarter < rem) {
        int r0 = __ldg(g_csrc + e + quarter);
        acc8(a, __ldg(P4 + r0 * 8 + sub));
    }
    #pragma unroll
    for (int i = 0; i < 8; i++) {
        a[i] += __shfl_xor_sync(0xffffffffu, a[i], 8);
        a[i] += __shfl_xor_sync(0xffffffffu, a[i], 16);
    }

    float o0 = 0.f, o1 = 0.f;
    if (quarter == 0) {
        float id = __ldg(g_invdeg + gw);
        float4 t0 = __ldg((const float4*)tmp + gw * 16 + sub * 2);
        float4 t1 = __ldg((const float4*)tmp + gw * 16 + sub * 2 + 1);
        float r[8];
        r[0] = t0.x + id * a[0]; r[1] = t0.y + id * a[1];
        r[2] = t0.z + id * a[2]; r[3] = t0.w + id * a[3];
        r[4] = t1.x + id * a[4]; r[5] = t1.y + id * a[5];
        r[6] = t1.z + id * a[6]; r[7] = t1.w + id * a[7];
        float4 w00 = __ldg((const float4*)Wout + sub * 2);
        float4 w01 = __ldg((const float4*)Wout + sub * 2 + 1);
        float4 w10 = __ldg((const float4*)(Wout + 64) + sub * 2);
        float4 w11 = __ldg((const float4*)(Wout + 64) + sub * 2 + 1);
        o0 = r[0] * w00.x + r[1] * w00.y + r[2] * w00.z + r[3] * w00.w
           + r[4] * w01.x + r[5] * w01.y + r[6] * w01.z + r[7] * w01.w;
        o1 = r[0] * w10.x + r[1] * w10.y + r[2] * w10.z + r[3] * w10.w
           + r[4] * w11.x + r[5] * w11.y + r[6] * w11.z + r[7] * w11.w;
    }
    // reduce over the 8 low lanes (higher lanes contribute 0)
    #pragma unroll
    for (int off = 4; off; off >>= 1) {
        o0 += __shfl_down_sync(0xffffffffu, o0, off);
        o1 += __shfl_down_sync(0xffffffffu, o1, off);
    }
    if (lane == 0) {
        out[gw * 2 + 0] = o0 + __ldg(bout + 0);
        out[gw * 2 + 1] = o1 + __ldg(bout + 1);
    }
}

// ---------------- launch: fork-join overlap of CSR build with layer-0 GEMM (R14) ----------------
extern "C" void kernel_launch(void* const* d_in, const int* in_sizes, int n_in,
                              void* d_out, int out_size) {
    const float* x    = (const float*)d_in[0];
    const int*   ei   = (const int*)d_in[1];
    const float* Wl   = (const float*)d_in[2];
    const float* bl   = (const float*)d_in[3];
    const float* Wr   = (const float*)d_in[4];
    const float* Wout = (const float*)d_in[5];
    const float* bout = (const float*)d_in[6];
    float* out = (float*)d_out;

    int n = in_sizes[0] / DD;
    int e = in_sizes[1] / 2;
    const int* src = ei;
    const int* dst = ei + e;

    float *hP, *tP;
    __half* pP;
    uint2* WfP;
    int *degP, *curP;
    cudaGetSymbolAddress((void**)&hP, g_h);
    cudaGetSymbolAddress((void**)&pP, g_p);
    cudaGetSymbolAddress((void**)&tP, g_tmp);
    cudaGetSymbolAddress((void**)&WfP, g_Wf);
    cudaGetSymbolAddress((void**)&degP, g_deg);
    cudaGetSymbolAddress((void**)&curP, g_cursor);

    int nb = (n + 1023) / 1024;
    int mma_blocks = (n + 63) / 64;
    int warp_blocks = (n + 7) / 8;

    cudaStream_t s1;
    cudaStreamCreateWithFlags(&s1, cudaStreamNonBlocking);
    cudaEvent_t evFork, evJoin;
    cudaEventCreateWithFlags(&evFork, cudaEventDisableTiming);
    cudaEventCreateWithFlags(&evJoin, cudaEventDisableTiming);

    // fork: side stream builds CSR while main stream does weights + layer-0 GEMM
    cudaEventRecord(evFork, 0);
    cudaStreamWaitEvent(s1, evFork, 0);

    cudaMemsetAsync(degP, 0, (size_t)n * sizeof(int), s1);
    cudaMemsetAsync(curP, 0, (size_t)n * sizeof(int), s1);
    k_prepW<<<(3 * 2048 + 255) / 256, 256>>>(Wr, Wl);                     // main
    k_count<<<(e + 255) / 256, 256, 0, s1>>>(dst, e);                     // side
    k_scanA<<<nb, 1024, 0, s1>>>(n);                                      // side
    k_mma<<<mma_blocks, 256>>>(x, WfP, bl, tP, pP, n);                    // main; ncu slot
    k_scanB<<<1, 128, 0, s1>>>(nb);                                       // side
    k_scanC<<<(n + 255) / 256, 256, 0, s1>>>(n, e);                       // side
    k_fill<<<(e + 255) / 256, 256, 0, s1>>>(src, dst, e);                 // side
    cudaEventRecord(evJoin, s1);

    // join: aggregation needs both CSR (side) and GEMM outputs (main)
    cudaStreamWaitEvent(0, evJoin, 0);
    k_aggr<<<warp_blocks, 256>>>(pP, tP, hP, n);

    k_mma<<<mma_blocks, 256>>>(hP, WfP + 2048, bl + 64, tP, pP, n);
    k_aggr<<<warp_blocks, 256>>>(pP, tP, hP, n);

    k_mma<<<mma_blocks, 256>>>(hP, WfP + 4096, bl + 128, tP, pP, n);
    k_aggr_out<<<warp_blocks, 256>>>(pP, tP, Wout, bout, out, n);

    cudaEventDestroy(evFork);
    cudaEventDestroy(evJoin);
    cudaStreamDestroy(s1);
}